// round 13
// baseline (speedup 1.0000x reference)
#include <cuda_runtime.h>
#include <cuda_bf16.h>
#include <cstdint>

// DIN fused kernels for sm_103a — round 12.
// K1: warp-specialized pipeline: 6 mma warps (bf16 mma.sync, 2 colgroups x 3
//     rowgroups) + 2 utility warps (cp.async issue, convert, gemv, softmax, ui).
//     Double-buffered XBF; named-barrier producer/consumer; everything hidden
//     under the mma.sync throughput floor.
// K2: fp32 MLP (known good).

#define S_LEN 200
#define E_DIM 128
#define XSTRB 272        // bf16 X row stride bytes (17 x 16B -> LDSM conflict-free)

// ---- K1 smem byte offsets ----
#define XBF0_OFF   0          // 208 x 136 bf16 = 56576 (rows 200-207 zero)
#define XBF1_OFF   56576
#define STG_OFF    113152     // 200x128 fp32 staging = 102400
#define STGC_OFF   215552     // staged cand = 512
#define VBUF_OFF   216064     // float[2][128]
#define PART_OFF   217088     // float[2][416] score partials
#define ATTN_OFF   220416     // float[208] raw exp weights
#define PART2_OFF  221248     // float[4][128] ui partials
#define RED_OFF    223296     // float[16]
#define B1_OFF     223360     // float[128]
#define W2S_OFF    223872     // float[128]
#define SMEM_REQ   224384

__device__ float g_ui[4096 * 128];   // user_interest

__device__ __forceinline__ uint32_t smem_u32(const void* p) {
    uint32_t a;
    asm("{ .reg .u64 t; cvta.to.shared.u64 t, %1; cvt.u32.u64 %0, t; }"
        : "=r"(a) : "l"(p));
    return a;
}
__device__ __forceinline__ uint32_t packbf(float lo, float hi) {
    uint32_t r;  // first f32 source -> high half
    asm("cvt.rn.bf16x2.f32 %0, %1, %2;" : "=r"(r) : "f"(hi), "f"(lo));
    return r;
}
__device__ __forceinline__ float2 bf2f(uint32_t u) {
    __nv_bfloat162 p = *reinterpret_cast<__nv_bfloat162*>(&u);
    return make_float2(__bfloat162float(p.x), __bfloat162float(p.y));
}
__device__ __forceinline__ void mma16(float* d, const uint32_t* a, const uint32_t* b) {
    asm volatile(
        "mma.sync.aligned.m16n8k16.row.col.f32.bf16.bf16.f32 "
        "{%0,%1,%2,%3}, {%4,%5,%6,%7}, {%8,%9}, {%0,%1,%2,%3};"
        : "+f"(d[0]), "+f"(d[1]), "+f"(d[2]), "+f"(d[3])
        : "r"(a[0]), "r"(a[1]), "r"(a[2]), "r"(a[3]), "r"(b[0]), "r"(b[1]));
}
__device__ __forceinline__ void ldsm4(uint32_t* r, uint32_t addr) {
    asm volatile("ldmatrix.sync.aligned.m8n8.x4.shared.b16 {%0,%1,%2,%3}, [%4];"
                 : "=r"(r[0]), "=r"(r[1]), "=r"(r[2]), "=r"(r[3]) : "r"(addr));
}

// Named barriers: BAR_X (id 1): utility arrives (XBF/vbuf ready), mma syncs.
// BAR_S (id 3): mma arrives (scores ready), utility syncs. PBAR (id 2): utility-only.
#define BARX_ARRIVE() asm volatile("bar.arrive 1, 256;" ::: "memory")
#define BARX_SYNC()   asm volatile("bar.sync   1, 256;" ::: "memory")
#define BARS_ARRIVE() asm volatile("bar.arrive 3, 256;" ::: "memory")
#define BARS_SYNC()   asm volatile("bar.sync   3, 256;" ::: "memory")
#define PBAR()        asm volatile("bar.sync   2, 64;"  ::: "memory")

// ---------------------------------------------------------------------------
// K1
// ---------------------------------------------------------------------------
__global__ __launch_bounds__(256, 1) void din_attn_kernel(
    const float* __restrict__ beh, const float* __restrict__ cand,
    const float* __restrict__ fc1w, const float* __restrict__ fc1b,
    const float* __restrict__ fc2w, int nb)
{
    extern __shared__ __align__(16) char Ab[];
    const uint32_t A = smem_u32(Ab);

    float* stgF  = (float*)(Ab + STG_OFF);
    float* candsS= (float*)(Ab + STGC_OFF);
    float* vbuf  = (float*)(Ab + VBUF_OFF);
    float* part  = (float*)(Ab + PART_OFF);
    float* attn  = (float*)(Ab + ATTN_OFF);
    float* part2 = (float*)(Ab + PART2_OFF);
    float* red   = (float*)(Ab + RED_OFF);
    float* b1s   = (float*)(Ab + B1_OFF);
    float* w2s   = (float*)(Ab + W2S_OFF);

    const int tid = threadIdx.x, wid = tid >> 5, lane = tid & 31;
    const int g = lane >> 2, t4 = lane & 3;
    const int stride = gridDim.x;
    const int b0 = blockIdx.x;
    if (b0 >= nb) return;

    const bool is_mma = (wid < 6);

    // ================= one-time init (all 256 threads) =================
    {   // stage W_b fp32 into staging region
        const float4* w4 = (const float4*)fc1w;
        float4* s4 = (float4*)stgF;
#pragma unroll
        for (int i = 0; i < 16; i++) s4[tid + i * 256] = w4[tid + i * 256];
    }
    __syncthreads();

    uint32_t Bf[8][8][2];
    const int wc = wid & 1, rg = wid >> 1;   // meaningful for mma warps
    if (is_mma) {
        const int n0 = wc * 64;
#pragma unroll
        for (int kt = 0; kt < 8; kt++)
#pragma unroll
            for (int nt = 0; nt < 8; nt++) {
                int n = n0 + nt * 8 + g;
                int r = kt * 16 + 2 * t4;
                Bf[kt][nt][0] = packbf(stgF[r * 128 + n],       stgF[(r + 1) * 128 + n]);
                Bf[kt][nt][1] = packbf(stgF[(r + 8) * 128 + n], stgF[(r + 9) * 128 + n]);
            }
    }
    if (tid < 128) { b1s[tid] = fc1b[tid]; w2s[tid] = fc2w[tid]; }
    for (int i = tid; i < 1088; i += 256) {
        *(uint16_t*)(Ab + XBF0_OFF + 200 * XSTRB + i * 2) = 0;
        *(uint16_t*)(Ab + XBF1_OFF + 200 * XSTRB + i * 2) = 0;
    }
    __syncthreads();   // staging consumed; phantom rows zeroed

    // ================= role split =================
    if (is_mma) {
        // ------------- 6 MMA warps -------------
        const int n0 = wc * 64;
        static const int mtb[4] = {0, 5, 9, 13};
        const int mt_begin = mtb[rg], mt_end = mtb[rg + 1];
        const uint32_t lm_lane = (uint32_t)(lane & 15) * XSTRB
                               + ((lane & 16) ? 16u : 0u);
        int i = 0;
        for (int b = b0; b < nb; b += stride, i++) {
            const int par = i & 1;
            BARX_SYNC();   // XBF[par] + vbuf[par] ready
            const float* vb = vbuf + par * 128;
            float* pt = part + par * 416;
            const uint32_t lm_base = A + (par ? XBF1_OFF : XBF0_OFF) + lm_lane;

            for (int mt = mt_begin; mt < mt_end; mt++) {
                uint32_t abase = lm_base + (uint32_t)mt * 16u * XSTRB;
                float acc[8][4];
#pragma unroll
                for (int nt = 0; nt < 8; nt++)
#pragma unroll
                    for (int j = 0; j < 4; j++) acc[nt][j] = 0.f;
#pragma unroll
                for (int kt = 0; kt < 8; kt++) {
                    uint32_t a[4];
                    ldsm4(a, abase + (uint32_t)kt * 32u);
#pragma unroll
                    for (int nt = 0; nt < 8; nt++)
                        mma16(acc[nt], a, Bf[kt][nt]);
                }
                float p0 = 0.f, p1 = 0.f;
#pragma unroll
                for (int nt = 0; nt < 8; nt++) {
                    int c = n0 + nt * 8 + 2 * t4;
                    float2 vv = *(const float2*)(vb + c);
                    float2 ww = *(const float2*)(w2s + c);
                    p0 += fmaxf(acc[nt][0] + vv.x, 0.f) * ww.x
                        + fmaxf(acc[nt][1] + vv.y, 0.f) * ww.y;
                    p1 += fmaxf(acc[nt][2] + vv.x, 0.f) * ww.x
                        + fmaxf(acc[nt][3] + vv.y, 0.f) * ww.y;
                }
                p0 += __shfl_xor_sync(0xffffffffu, p0, 1);
                p0 += __shfl_xor_sync(0xffffffffu, p0, 2);
                p1 += __shfl_xor_sync(0xffffffffu, p1, 1);
                p1 += __shfl_xor_sync(0xffffffffu, p1, 2);
                if (t4 == 0) {
                    int r_lo = mt * 16 + g, r_hi = mt * 16 + 8 + g;
                    pt[wc * 208 + r_lo] = p0;
                    if (r_hi < S_LEN) pt[wc * 208 + r_hi] = p1;
                }
            }
            BARS_ARRIVE();   // scores(b) ready
        }
    } else {
        // ------------- 2 utility warps (tid 192..255) -------------
        const int ptid = tid - 192;          // 0..63
        const int uwarp = wid - 6;           // 0/1

        auto issue_load = [&](int b) {
            const float4* src = (const float4*)(beh + (size_t)b * (S_LEN * E_DIM));
#pragma unroll 5
            for (int k = 0; k < 50; k++) {
                int j = 2 * (ptid + (k << 6));
                uint32_t dst = A + STG_OFF + (uint32_t)j * 16u;
                asm volatile("cp.async.cg.shared.global [%0], [%1], 16;"
                             :: "r"(dst), "l"(src + j) : "memory");
                asm volatile("cp.async.cg.shared.global [%0], [%1], 16;"
                             :: "r"(dst + 16u), "l"(src + j + 1) : "memory");
            }
            if (ptid < 32)
                asm volatile("cp.async.cg.shared.global [%0], [%1], 16;"
                             :: "r"(A + STGC_OFF + (uint32_t)ptid * 16u),
                                "l"((const float4*)(cand + (size_t)b * 128) + ptid)
                             : "memory");
        };
        auto convert_gemv = [&](int buf) {
            // convert: self-consistent thread mapping (same i's as issue_load)
            char* xb = Ab + (buf ? XBF1_OFF : XBF0_OFF);
#pragma unroll 5
            for (int k = 0; k < 50; k++) {
                int i = ptid + (k << 6);
                const float4* s4 = (const float4*)stgF + 2 * i;
                float4 v0 = s4[0], v1 = s4[1];
                int s = i >> 4, e0 = (i & 15) * 8;
                *(uint4*)(xb + (uint32_t)s * XSTRB + (uint32_t)e0 * 2) =
                    make_uint4(packbf(v0.x, v0.y), packbf(v0.z, v0.w),
                               packbf(v1.x, v1.y), packbf(v1.z, v1.w));
            }
            // gemv: v[n] = cand @ W_c[:,n] + b1[n], 2 rows per thread, W_c from L2
            int n = 2 * ptid;
            float a0 = 0.f, a1 = 0.f;
            const float* wcol = fc1w + 128 * 128 + n;
#pragma unroll 4
            for (int e = 0; e < 128; e++) {
                float c = candsS[e];
                float2 wv = *(const float2*)(wcol + e * 128);
                a0 += c * wv.x;
                a1 += c * wv.y;
            }
            float* vb = vbuf + buf * 128;
            vb[n]     = a0 + b1s[n];
            vb[n + 1] = a1 + b1s[n + 1];
        };

        // prologue: fill XBF[0]/vbuf[0] for b0; prefetch b0+stride
        issue_load(b0);
        asm volatile("cp.async.commit_group;" ::: "memory");
        asm volatile("cp.async.wait_group 0;" ::: "memory");
        PBAR();
        convert_gemv(0);
        BARX_ARRIVE();
        if (b0 + stride < nb) {
            issue_load(b0 + stride);
            asm volatile("cp.async.commit_group;" ::: "memory");
        }

        int i = 0;
        for (int b = b0; b < nb; b += stride, i++) {
            const int par = i & 1;
            // prepare batch b+stride (overlaps mma(b))
            if (b + stride < nb) {
                asm volatile("cp.async.wait_group 0;" ::: "memory");
                PBAR();
                convert_gemv(par ^ 1);
                BARX_ARRIVE();
                if (b + 2 * stride < nb) {
                    issue_load(b + 2 * stride);
                    asm volatile("cp.async.commit_group;" ::: "memory");
                }
            }
            // consume scores(b)
            BARS_SYNC();
            const float* pt = part + par * 416;

            // softmax (max-free; scores bounded ~|9|): raw exp + sum
            float lsum = 0.f;
#pragma unroll
            for (int j = 0; j < 4; j++) {
                int s = ptid + 64 * j;
                if (s < S_LEN) {
                    float e = __expf(pt[s] + pt[208 + s]);
                    attn[s] = e;
                    lsum += e;
                }
            }
#pragma unroll
            for (int o = 16; o; o >>= 1)
                lsum += __shfl_xor_sync(0xffffffffu, lsum, o);
            if (lane == 0) red[uwarp] = lsum;
            PBAR();
            const float inv = 1.f / (red[0] + red[1]);

            // ui: 4 rowgroups x 50 rows; 8 e-values per thread
            {
                int e8 = (ptid & 15) * 8;
                int h = ptid >> 4;
                const char* xb = Ab + (par ? XBF1_OFF : XBF0_OFF);
                float a0=0.f,a1=0.f,a2=0.f,a3=0.f,a4=0.f,a5=0.f,a6=0.f,a7=0.f;
                int s0 = h * 50;
#pragma unroll 5
                for (int s = s0; s < s0 + 50; s++) {
                    float w = attn[s];
                    uint4 xv = *(const uint4*)(xb + (uint32_t)s * XSTRB + (uint32_t)e8 * 2);
                    float2 q0 = bf2f(xv.x), q1 = bf2f(xv.y);
                    float2 q2 = bf2f(xv.z), q3 = bf2f(xv.w);
                    a0 += w * q0.x; a1 += w * q0.y;
                    a2 += w * q1.x; a3 += w * q1.y;
                    a4 += w * q2.x; a5 += w * q2.y;
                    a6 += w * q3.x; a7 += w * q3.y;
                }
                *(float4*)(part2 + h * 128 + e8)     = make_float4(a0, a1, a2, a3);
                *(float4*)(part2 + h * 128 + e8 + 4) = make_float4(a4, a5, a6, a7);
                PBAR();
                int e2 = ptid * 2;
                float s0v = (part2[e2]     + part2[128 + e2])
                          + (part2[256 + e2] + part2[384 + e2]);
                float s1v = (part2[e2 + 1] + part2[129 + e2])
                          + (part2[257 + e2] + part2[385 + e2]);
                g_ui[(size_t)b * 128 + e2]     = s0v * inv;
                g_ui[(size_t)b * 128 + e2 + 1] = s1v * inv;
                PBAR();   // part2/attn free for next iteration
            }
        }
    }
}

// ---------------------------------------------------------------------------
// K2: logit[r] = relu([ui|cand]@mlp1 + b1) @ mlp2 + b2   (fp32)
// ---------------------------------------------------------------------------
#define K2_SMEM (32 * 256 * 4 + 2 * 16 * 256 * 4)   // 65536

__global__ __launch_bounds__(256, 1) void din_mlp_kernel(
    const float* __restrict__ cand,
    const float* __restrict__ w1, const float* __restrict__ b1,
    const float* __restrict__ w2, const float* __restrict__ b2,
    float* __restrict__ out, int nb)
{
    extern __shared__ __align__(16) float s2[];
    float* xs = s2;              // 32 x 256
    float* ws = s2 + 8192;       // 2 x 16 x 256
    const uint32_t wsA = smem_u32(ws);

    const int tid = threadIdx.x, lane = tid & 31, w = tid >> 5;
    const int rb = blockIdx.x * 32;

#pragma unroll
    for (int i = 0; i < 4; i++) {
        int idx = tid + i * 256;
        int r = idx >> 5, c4 = idx & 31;
        ((float4*)xs)[r * 64 + c4]      = ((const float4*)(g_ui + (size_t)(rb + r) * 128))[c4];
        ((float4*)xs)[r * 64 + 32 + c4] = ((const float4*)(cand + (size_t)(rb + r) * 128))[c4];
    }

    auto issue = [&](int kt, int buf) {
        const float4* src = (const float4*)(w1 + (size_t)kt * 4096);
        uint32_t dst = wsA + (uint32_t)buf * 16384u + (uint32_t)tid * 16u;
#pragma unroll
        for (int i = 0; i < 4; i++)
            asm volatile("cp.async.cg.shared.global [%0], [%1], 16;"
                         :: "r"(dst + i * 4096u), "l"(src + tid + i * 256) : "memory");
    };
    issue(0, 0);
    asm volatile("cp.async.commit_group;" ::: "memory");

    float b1l[8], w2l[8];
#pragma unroll
    for (int j = 0; j < 8; j++) {
        b1l[j] = b1[lane * 8 + j];
        w2l[j] = w2[lane * 8 + j];
    }
    float acc[4][8];
#pragma unroll
    for (int i = 0; i < 4; i++)
#pragma unroll
        for (int j = 0; j < 8; j++) acc[i][j] = 0.f;

    for (int kt = 0; kt < 16; kt++) {
        asm volatile("cp.async.wait_group 0;" ::: "memory");
        __syncthreads();
        if (kt < 15) {
            issue(kt + 1, (kt + 1) & 1);
            asm volatile("cp.async.commit_group;" ::: "memory");
        }
        const float* wt = ws + (kt & 1) * 4096;
#pragma unroll
        for (int kk = 0; kk < 16; kk++) {
            int k = kt * 16 + kk;
            float x0 = xs[(4 * w + 0) * 256 + k];
            float x1 = xs[(4 * w + 1) * 256 + k];
            float x2 = xs[(4 * w + 2) * 256 + k];
            float x3 = xs[(4 * w + 3) * 256 + k];
            float4 a4 = *(const float4*)(wt + kk * 256 + lane * 8);
            float4 c4 = *(const float4*)(wt + kk * 256 + lane * 8 + 4);
            float wb[8] = {a4.x, a4.y, a4.z, a4.w, c4.x, c4.y, c4.z, c4.w};
#pragma unroll
            for (int j = 0; j < 8; j++) {
                acc[0][j] += x0 * wb[j];
                acc[1][j] += x1 * wb[j];
                acc[2][j] += x2 * wb[j];
                acc[3][j] += x3 * wb[j];
            }
        }
    }

    float p[4];
#pragma unroll
    for (int i = 0; i < 4; i++) {
        float s = 0.f;
#pragma unroll
        for (int j = 0; j < 8; j++)
            s += fmaxf(acc[i][j] + b1l[j], 0.f) * w2l[j];
        p[i] = s;
    }
#pragma unroll
    for (int o = 16; o; o >>= 1) {
#pragma unroll
        for (int i = 0; i < 4; i++)
            p[i] += __shfl_xor_sync(0xffffffffu, p[i], o);
    }
    if (lane == 0) {
        float bb = b2[0];
#pragma unroll
        for (int i = 0; i < 4; i++)
            out[rb + 4 * w + i] = p[i] + bb;
    }
}

// ---------------------------------------------------------------------------
extern "C" void kernel_launch(void* const* d_in, const int* in_sizes, int n_in,
                              void* d_out, int out_size)
{
    const float* beh  = (const float*)d_in[0];
    const float* cand = (const float*)d_in[1];
    const float* fc1w = (const float*)d_in[2];
    const float* fc1b = (const float*)d_in[3];
    const float* fc2w = (const float*)d_in[4];
    // d_in[5] = fc2_b: softmax shift-invariant, unused.
    const float* m1w  = (const float*)d_in[6];
    const float* m1b  = (const float*)d_in[7];
    const float* m2w  = (const float*)d_in[8];
    const float* m2b  = (const float*)d_in[9];
    float* out = (float*)d_out;

    const int nb = in_sizes[1] / 128;   // 4096

    int sms = 148;
    cudaDeviceGetAttribute(&sms, cudaDevAttrMultiProcessorCount, 0);

    cudaFuncSetAttribute(din_attn_kernel,
                         cudaFuncAttributeMaxDynamicSharedMemorySize, SMEM_REQ);
    cudaFuncSetAttribute(din_mlp_kernel,
                         cudaFuncAttributeMaxDynamicSharedMemorySize, K2_SMEM);

    int grid1 = sms < nb ? sms : nb;
    din_attn_kernel<<<grid1, 256, SMEM_REQ>>>(beh, cand, fc1w, fc1b, fc2w, nb);

    din_mlp_kernel<<<nb / 32, 256, K2_SMEM>>>(cand, m1w, m1b, m2w, m2b, out, nb);
}

// round 14
// speedup vs baseline: 1.9826x; 1.9826x over previous
#include <cuda_runtime.h>
#include <cuda_bf16.h>
#include <cstdint>

// DIN fused kernels for sm_103a — round 13.
// K1: warp-specialized, SMSP-balanced: 4 mma warps (one per SMSP; bf16
//     mma.sync) + 4 utility warps (cp.async, convert, softmax, ui).
//     v = cand@W_c + b1 precomputed into g_v during init (no gemv in loop).
// K2: fp32 MLP (known good).

#define S_LEN 200
#define E_DIM 128
#define XSTRB 272        // bf16 X row stride bytes (17 x 16B -> LDSM conflict-free)

// ---- K1 smem byte offsets ----
#define XBF0_OFF   0          // 208 x 136 bf16 = 56576 (rows 200-207 zero)
#define XBF1_OFF   56576
#define STG_OFF    113152     // 102400: X fp32 staging; W_b / W_c^T scratch in init
#define STGV_OFF   215552     // 512: staged v(b+1)
#define VB_OFF     216064     // float[2][128]
#define PART_OFF   217088     // float[2][416] score partials (cand scratch in init)
#define ATTN_OFF   220416     // float[208] raw exp weights
#define PART2_OFF  221248     // float[8][128] ui partials
#define RED_OFF    225344     // float[16]
#define W2S_OFF    225408     // float[128]
#define SMEM_REQ   225920

__device__ float g_ui[4096 * 128];   // user_interest
__device__ float g_v[4096 * 128];    // candidate projection v = cand@W_c + b1

__device__ __forceinline__ uint32_t smem_u32(const void* p) {
    uint32_t a;
    asm("{ .reg .u64 t; cvta.to.shared.u64 t, %1; cvt.u32.u64 %0, t; }"
        : "=r"(a) : "l"(p));
    return a;
}
__device__ __forceinline__ uint32_t packbf(float lo, float hi) {
    uint32_t r;  // first f32 source -> high half
    asm("cvt.rn.bf16x2.f32 %0, %1, %2;" : "=r"(r) : "f"(hi), "f"(lo));
    return r;
}
__device__ __forceinline__ float2 bf2f(uint32_t u) {
    __nv_bfloat162 p = *reinterpret_cast<__nv_bfloat162*>(&u);
    return make_float2(__bfloat162float(p.x), __bfloat162float(p.y));
}
__device__ __forceinline__ void mma16(float* d, const uint32_t* a, const uint32_t* b) {
    asm volatile(
        "mma.sync.aligned.m16n8k16.row.col.f32.bf16.bf16.f32 "
        "{%0,%1,%2,%3}, {%4,%5,%6,%7}, {%8,%9}, {%0,%1,%2,%3};"
        : "+f"(d[0]), "+f"(d[1]), "+f"(d[2]), "+f"(d[3])
        : "r"(a[0]), "r"(a[1]), "r"(a[2]), "r"(a[3]), "r"(b[0]), "r"(b[1]));
}
__device__ __forceinline__ void ldsm4(uint32_t* r, uint32_t addr) {
    asm volatile("ldmatrix.sync.aligned.m8n8.x4.shared.b16 {%0,%1,%2,%3}, [%4];"
                 : "=r"(r[0]), "=r"(r[1]), "=r"(r[2]), "=r"(r[3]) : "r"(addr));
}

// BARX (id1): utility arrives (XBF/VB ready), mma syncs. BARS (id3): mma arrives
// (scores ready), utility syncs. PBAR (id2): utility-internal (128 threads).
#define BARX_ARRIVE() asm volatile("bar.arrive 1, 256;" ::: "memory")
#define BARX_SYNC()   asm volatile("bar.sync   1, 256;" ::: "memory")
#define BARS_ARRIVE() asm volatile("bar.arrive 3, 256;" ::: "memory")
#define BARS_SYNC()   asm volatile("bar.sync   3, 256;" ::: "memory")
#define PBAR()        asm volatile("bar.sync   2, 128;" ::: "memory")

// ---------------------------------------------------------------------------
// K1
// ---------------------------------------------------------------------------
__global__ __launch_bounds__(256, 1) void din_attn_kernel(
    const float* __restrict__ beh, const float* __restrict__ cand,
    const float* __restrict__ fc1w, const float* __restrict__ fc1b,
    const float* __restrict__ fc2w, int nb)
{
    extern __shared__ __align__(16) char Ab[];
    const uint32_t A = smem_u32(Ab);

    float* stgF  = (float*)(Ab + STG_OFF);
    float* stgv  = (float*)(Ab + STGV_OFF);
    float* VB    = (float*)(Ab + VB_OFF);
    float* part  = (float*)(Ab + PART_OFF);
    float* attn  = (float*)(Ab + ATTN_OFF);
    float* part2 = (float*)(Ab + PART2_OFF);
    float* red   = (float*)(Ab + RED_OFF);
    float* w2s   = (float*)(Ab + W2S_OFF);

    const int tid = threadIdx.x, wid = tid >> 5, lane = tid & 31;
    const int g = lane >> 2, t4 = lane & 3;
    const int stride = gridDim.x;
    const int b0 = blockIdx.x;
    if (b0 >= nb) return;

    const bool is_mma = (wid < 4);

    // ================= one-time init (all 256 threads) =================
    {   // stage W_b fp32 (64KB) into staging region
        const float4* w4 = (const float4*)fc1w;
        float4* s4 = (float4*)stgF;
#pragma unroll
        for (int i = 0; i < 16; i++) s4[tid + i * 256] = w4[tid + i * 256];
    }
    __syncthreads();

    uint32_t Bf[8][8][2];
    const int wc = wid & 1, rh = wid >> 1;   // mma warps: colgroup, row-half
    if (is_mma) {
        const int n0 = wc * 64;
#pragma unroll
        for (int kt = 0; kt < 8; kt++)
#pragma unroll
            for (int nt = 0; nt < 8; nt++) {
                int n = n0 + nt * 8 + g;
                int r = kt * 16 + 2 * t4;
                Bf[kt][nt][0] = packbf(stgF[r * 128 + n],       stgF[(r + 1) * 128 + n]);
                Bf[kt][nt][1] = packbf(stgF[(r + 8) * 128 + n], stgF[(r + 9) * 128 + n]);
            }
    }
    if (tid < 128) w2s[tid] = fc2w[tid];
    __syncthreads();   // W_b staging consumed

    // stage W_c transposed [n][130] fp32 into staging; zero phantom X rows
    for (int idx = tid; idx < 128 * 128; idx += 256) {
        int e = idx >> 7, n = idx & 127;
        stgF[n * 130 + e] = fc1w[128 * 128 + idx];
    }
    for (int i = tid; i < 1088; i += 256) {
        *(uint16_t*)(Ab + XBF0_OFF + 200 * XSTRB + i * 2) = 0;
        *(uint16_t*)(Ab + XBF1_OFF + 200 * XSTRB + i * 2) = 0;
    }
    __syncthreads();

    // ---- precompute v for this CTA's batches -> g_v ----
    {
        float* candsc = part;   // [2][128] scratch
        if (tid < 32)
            asm volatile("cp.async.cg.shared.global [%0], [%1], 16;"
                         :: "r"(A + PART_OFF + (uint32_t)tid * 16u),
                            "l"((const float4*)(cand + (size_t)b0 * 128) + tid)
                         : "memory");
        asm volatile("cp.async.commit_group;" ::: "memory");
        int i = 0;
        for (int b = b0; b < nb; b += stride, i++) {
            asm volatile("cp.async.wait_group 0;" ::: "memory");
            __syncthreads();
            int pr = i & 1;
            if (b + stride < nb && tid < 32)
                asm volatile("cp.async.cg.shared.global [%0], [%1], 16;"
                             :: "r"(A + PART_OFF + (uint32_t)((pr ^ 1) * 512 + tid * 16)),
                                "l"((const float4*)(cand + (size_t)(b + stride) * 128) + tid)
                             : "memory");
            asm volatile("cp.async.commit_group;" ::: "memory");
            int n = tid >> 1, h2 = tid & 1;
            const float* wr = stgF + n * 130 + h2 * 64;
            const float* cd = candsc + pr * 128 + h2 * 64;
            float a = 0.f;
#pragma unroll 8
            for (int k = 0; k < 64; k++) a += cd[k] * wr[k];
            a += __shfl_xor_sync(0xffffffffu, a, 1);
            if (h2 == 0) g_v[(size_t)b * 128 + n] = a + fc1b[n];
        }
        __syncthreads();
    }

    // ================= role split =================
    if (is_mma) {
        // ------------- 4 MMA warps, one per SMSP -------------
        const int n0 = wc * 64;
        const int mt_begin = rh ? 7 : 0;
        const int mt_end   = rh ? 13 : 7;
        const uint32_t lm_lane = (uint32_t)(lane & 15) * XSTRB
                               + ((lane & 16) ? 16u : 0u);
        int i = 0;
        for (int b = b0; b < nb; b += stride, i++) {
            const int par = i & 1;
            BARX_SYNC();   // XBF[par] + VB[par] ready
            const float* vb = VB + par * 128;
            float* pt = part + par * 416;
            const uint32_t lm_base = A + (par ? XBF1_OFF : XBF0_OFF) + lm_lane;

            for (int mt = mt_begin; mt < mt_end; mt++) {
                uint32_t abase = lm_base + (uint32_t)mt * 16u * XSTRB;
                float acc[8][4];
#pragma unroll
                for (int nt = 0; nt < 8; nt++)
#pragma unroll
                    for (int j = 0; j < 4; j++) acc[nt][j] = 0.f;
#pragma unroll
                for (int kt = 0; kt < 8; kt++) {
                    uint32_t a[4];
                    ldsm4(a, abase + (uint32_t)kt * 32u);
#pragma unroll
                    for (int nt = 0; nt < 8; nt++)
                        mma16(acc[nt], a, Bf[kt][nt]);
                }
                float p0 = 0.f, p1 = 0.f;
#pragma unroll
                for (int nt = 0; nt < 8; nt++) {
                    int c = n0 + nt * 8 + 2 * t4;
                    float2 vv = *(const float2*)(vb + c);
                    float2 ww = *(const float2*)(w2s + c);
                    p0 += fmaxf(acc[nt][0] + vv.x, 0.f) * ww.x
                        + fmaxf(acc[nt][1] + vv.y, 0.f) * ww.y;
                    p1 += fmaxf(acc[nt][2] + vv.x, 0.f) * ww.x
                        + fmaxf(acc[nt][3] + vv.y, 0.f) * ww.y;
                }
                p0 += __shfl_xor_sync(0xffffffffu, p0, 1);
                p0 += __shfl_xor_sync(0xffffffffu, p0, 2);
                p1 += __shfl_xor_sync(0xffffffffu, p1, 1);
                p1 += __shfl_xor_sync(0xffffffffu, p1, 2);
                if (t4 == 0) {
                    int r_lo = mt * 16 + g, r_hi = mt * 16 + 8 + g;
                    pt[wc * 208 + r_lo] = p0;
                    if (r_hi < S_LEN) pt[wc * 208 + r_hi] = p1;
                }
            }
            BARS_ARRIVE();   // scores(b) ready
        }
    } else {
        // ------------- 4 utility warps (tid 128..255) -------------
        const int ptid = tid - 128;          // 0..127
        const int uwarp = wid - 4;           // 0..3

        auto issue_load = [&](int b) {
            const float4* src = (const float4*)(beh + (size_t)b * (S_LEN * E_DIM));
#pragma unroll 5
            for (int k = 0; k < 50; k++) {
                int j = ptid + (k << 7);
                asm volatile("cp.async.cg.shared.global [%0], [%1], 16;"
                             :: "r"(A + STG_OFF + (uint32_t)j * 16u), "l"(src + j)
                             : "memory");
            }
            if (ptid < 32)
                asm volatile("cp.async.cg.shared.global [%0], [%1], 16;"
                             :: "r"(A + STGV_OFF + (uint32_t)ptid * 16u),
                                "l"((const float4*)(g_v + (size_t)b * 128) + ptid)
                             : "memory");
        };
        auto convert_v = [&](int buf) {
            char* xb = Ab + (buf ? XBF1_OFF : XBF0_OFF);
#pragma unroll 5
            for (int k = 0; k < 25; k++) {
                int i = ptid + (k << 7);
                const float4* s4 = (const float4*)stgF + 2 * i;
                float4 v0 = s4[0], v1 = s4[1];
                int s = i >> 4, e0 = (i & 15) * 8;
                *(uint4*)(xb + (uint32_t)s * XSTRB + (uint32_t)e0 * 2) =
                    make_uint4(packbf(v0.x, v0.y), packbf(v0.z, v0.w),
                               packbf(v1.x, v1.y), packbf(v1.z, v1.w));
            }
            VB[buf * 128 + ptid] = stgv[ptid];
        };

        // prologue
        issue_load(b0);
        asm volatile("cp.async.commit_group;" ::: "memory");
        asm volatile("cp.async.wait_group 0;" ::: "memory");
        PBAR();
        convert_v(0);
        PBAR();            // convert done before staging reuse
        BARX_ARRIVE();
        if (b0 + stride < nb) {
            issue_load(b0 + stride);
            asm volatile("cp.async.commit_group;" ::: "memory");
        }

        int i = 0;
        for (int b = b0; b < nb; b += stride, i++) {
            const int par = i & 1;
            if (b + stride < nb) {
                asm volatile("cp.async.wait_group 0;" ::: "memory");
                PBAR();
                convert_v(par ^ 1);
                PBAR();    // convert reads of STG done before reissue below
                BARX_ARRIVE();
                if (b + 2 * stride < nb) {
                    issue_load(b + 2 * stride);
                    asm volatile("cp.async.commit_group;" ::: "memory");
                }
            }
            // consume scores(b)
            BARS_SYNC();
            const float* pt = part + par * 416;

            // max-free softmax (scores bounded ~|9|)
            float lsum = 0.f;
#pragma unroll
            for (int j = 0; j < 2; j++) {
                int s = ptid + 128 * j;
                if (s < S_LEN) {
                    float e = __expf(pt[s] + pt[208 + s]);
                    attn[s] = e;
                    lsum += e;
                }
            }
#pragma unroll
            for (int o = 16; o; o >>= 1)
                lsum += __shfl_xor_sync(0xffffffffu, lsum, o);
            if (lane == 0) red[uwarp] = lsum;
            PBAR();
            const float inv = 1.f / (red[0] + red[1] + red[2] + red[3]);

            // ui: 8 rowgroups x 25 rows; 8 e-values per thread
            {
                int e8 = (ptid & 15) * 8;
                int h = ptid >> 4;
                const char* xb = Ab + (par ? XBF1_OFF : XBF0_OFF);
                float a0=0.f,a1=0.f,a2=0.f,a3=0.f,a4=0.f,a5=0.f,a6=0.f,a7=0.f;
                int s0 = h * 25;
#pragma unroll 5
                for (int s = s0; s < s0 + 25; s++) {
                    float w = attn[s];
                    uint4 xv = *(const uint4*)(xb + (uint32_t)s * XSTRB + (uint32_t)e8 * 2);
                    float2 q0 = bf2f(xv.x), q1 = bf2f(xv.y);
                    float2 q2 = bf2f(xv.z), q3 = bf2f(xv.w);
                    a0 += w * q0.x; a1 += w * q0.y;
                    a2 += w * q1.x; a3 += w * q1.y;
                    a4 += w * q2.x; a5 += w * q2.y;
                    a6 += w * q3.x; a7 += w * q3.y;
                }
                *(float4*)(part2 + h * 128 + e8)     = make_float4(a0, a1, a2, a3);
                *(float4*)(part2 + h * 128 + e8 + 4) = make_float4(a4, a5, a6, a7);
                PBAR();
                float s = 0.f;
#pragma unroll
                for (int hh = 0; hh < 8; hh++) s += part2[hh * 128 + ptid];
                g_ui[(size_t)b * 128 + ptid] = s * inv;
                PBAR();   // attn/part2 free for next iteration
            }
        }
    }
}

// ---------------------------------------------------------------------------
// K2: logit[r] = relu([ui|cand]@mlp1 + b1) @ mlp2 + b2   (fp32)
// ---------------------------------------------------------------------------
#define K2_SMEM (32 * 256 * 4 + 2 * 16 * 256 * 4)   // 65536

__global__ __launch_bounds__(256, 1) void din_mlp_kernel(
    const float* __restrict__ cand,
    const float* __restrict__ w1, const float* __restrict__ b1,
    const float* __restrict__ w2, const float* __restrict__ b2,
    float* __restrict__ out, int nb)
{
    extern __shared__ __align__(16) float s2[];
    float* xs = s2;              // 32 x 256
    float* ws = s2 + 8192;       // 2 x 16 x 256
    const uint32_t wsA = smem_u32(ws);

    const int tid = threadIdx.x, lane = tid & 31, w = tid >> 5;
    const int rb = blockIdx.x * 32;

#pragma unroll
    for (int i = 0; i < 4; i++) {
        int idx = tid + i * 256;
        int r = idx >> 5, c4 = idx & 31;
        ((float4*)xs)[r * 64 + c4]      = ((const float4*)(g_ui + (size_t)(rb + r) * 128))[c4];
        ((float4*)xs)[r * 64 + 32 + c4] = ((const float4*)(cand + (size_t)(rb + r) * 128))[c4];
    }

    auto issue = [&](int kt, int buf) {
        const float4* src = (const float4*)(w1 + (size_t)kt * 4096);
        uint32_t dst = wsA + (uint32_t)buf * 16384u + (uint32_t)tid * 16u;
#pragma unroll
        for (int i = 0; i < 4; i++)
            asm volatile("cp.async.cg.shared.global [%0], [%1], 16;"
                         :: "r"(dst + i * 4096u), "l"(src + tid + i * 256) : "memory");
    };
    issue(0, 0);
    asm volatile("cp.async.commit_group;" ::: "memory");

    float b1l[8], w2l[8];
#pragma unroll
    for (int j = 0; j < 8; j++) {
        b1l[j] = b1[lane * 8 + j];
        w2l[j] = w2[lane * 8 + j];
    }
    float acc[4][8];
#pragma unroll
    for (int i = 0; i < 4; i++)
#pragma unroll
        for (int j = 0; j < 8; j++) acc[i][j] = 0.f;

    for (int kt = 0; kt < 16; kt++) {
        asm volatile("cp.async.wait_group 0;" ::: "memory");
        __syncthreads();
        if (kt < 15) {
            issue(kt + 1, (kt + 1) & 1);
            asm volatile("cp.async.commit_group;" ::: "memory");
        }
        const float* wt = ws + (kt & 1) * 4096;
#pragma unroll
        for (int kk = 0; kk < 16; kk++) {
            int k = kt * 16 + kk;
            float x0 = xs[(4 * w + 0) * 256 + k];
            float x1 = xs[(4 * w + 1) * 256 + k];
            float x2 = xs[(4 * w + 2) * 256 + k];
            float x3 = xs[(4 * w + 3) * 256 + k];
            float4 a4 = *(const float4*)(wt + kk * 256 + lane * 8);
            float4 c4 = *(const float4*)(wt + kk * 256 + lane * 8 + 4);
            float wb[8] = {a4.x, a4.y, a4.z, a4.w, c4.x, c4.y, c4.z, c4.w};
#pragma unroll
            for (int j = 0; j < 8; j++) {
                acc[0][j] += x0 * wb[j];
                acc[1][j] += x1 * wb[j];
                acc[2][j] += x2 * wb[j];
                acc[3][j] += x3 * wb[j];
            }
        }
    }

    float p[4];
#pragma unroll
    for (int i = 0; i < 4; i++) {
        float s = 0.f;
#pragma unroll
        for (int j = 0; j < 8; j++)
            s += fmaxf(acc[i][j] + b1l[j], 0.f) * w2l[j];
        p[i] = s;
    }
#pragma unroll
    for (int o = 16; o; o >>= 1) {
#pragma unroll
        for (int i = 0; i < 4; i++)
            p[i] += __shfl_xor_sync(0xffffffffu, p[i], o);
    }
    if (lane == 0) {
        float bb = b2[0];
#pragma unroll
        for (int i = 0; i < 4; i++)
            out[rb + 4 * w + i] = p[i] + bb;
    }
}

// ---------------------------------------------------------------------------
extern "C" void kernel_launch(void* const* d_in, const int* in_sizes, int n_in,
                              void* d_out, int out_size)
{
    const float* beh  = (const float*)d_in[0];
    const float* cand = (const float*)d_in[1];
    const float* fc1w = (const float*)d_in[2];
    const float* fc1b = (const float*)d_in[3];
    const float* fc2w = (const float*)d_in[4];
    // d_in[5] = fc2_b: softmax shift-invariant, unused.
    const float* m1w  = (const float*)d_in[6];
    const float* m1b  = (const float*)d_in[7];
    const float* m2w  = (const float*)d_in[8];
    const float* m2b  = (const float*)d_in[9];
    float* out = (float*)d_out;

    const int nb = in_sizes[1] / 128;   // 4096

    int sms = 148;
    cudaDeviceGetAttribute(&sms, cudaDevAttrMultiProcessorCount, 0);

    cudaFuncSetAttribute(din_attn_kernel,
                         cudaFuncAttributeMaxDynamicSharedMemorySize, SMEM_REQ);
    cudaFuncSetAttribute(din_mlp_kernel,
                         cudaFuncAttributeMaxDynamicSharedMemorySize, K2_SMEM);

    int grid1 = sms < nb ? sms : nb;
    din_attn_kernel<<<grid1, 256, SMEM_REQ>>>(beh, cand, fc1w, fc1b, fc2w, nb);

    din_mlp_kernel<<<nb / 32, 256, K2_SMEM>>>(cand, m1w, m1b, m2w, m2b, out, nb);
}

// round 15
// speedup vs baseline: 2.0013x; 1.0094x over previous
#include <cuda_runtime.h>
#include <cuda_bf16.h>
#include <cstdint>

// DIN fused kernels for sm_103a — round 14.
// K1: warp-specialized, SMSP-balanced: 4 mma warps (one per SMSP), each owning
//     32 h-cols x ALL rows (416 HMMA each, perfectly balanced), fully unrolled
//     mt loop; 4 utility warps (cp.async, convert, softmax, ui).
//     v = cand@W_c + b1 precomputed into g_v during init.
// K2: fp32 MLP (known good, unchanged).

#define S_LEN 200
#define E_DIM 128
#define XSTRB 272        // bf16 X row stride bytes (17 x 16B -> LDSM conflict-free)

// ---- K1 smem byte offsets ----
#define XBF0_OFF   0          // 208 x 136 bf16 = 56576 (rows 200-207 zero)
#define XBF1_OFF   56576
#define STG_OFF    113152     // 102400: X fp32 staging; W_b / W_c^T scratch in init
#define STGV_OFF   215552     // 512: staged v(b+1)
#define VB_OFF     216064     // float[2][128]
#define PART_OFF   217088     // float[2][832] score partials (cand scratch in init)
#define ATTN_OFF   223744     // float[208] raw exp weights
#define PART2_OFF  224576     // float[8][128] ui partials
#define RED_OFF    228672     // float[16]
#define SMEM_REQ   228736

__device__ float g_ui[4096 * 128];   // user_interest
__device__ float g_v[4096 * 128];    // candidate projection v = cand@W_c + b1

__device__ __forceinline__ uint32_t smem_u32(const void* p) {
    uint32_t a;
    asm("{ .reg .u64 t; cvta.to.shared.u64 t, %1; cvt.u32.u64 %0, t; }"
        : "=r"(a) : "l"(p));
    return a;
}
__device__ __forceinline__ uint32_t packbf(float lo, float hi) {
    uint32_t r;  // first f32 source -> high half
    asm("cvt.rn.bf16x2.f32 %0, %1, %2;" : "=r"(r) : "f"(hi), "f"(lo));
    return r;
}
__device__ __forceinline__ float2 bf2f(uint32_t u) {
    __nv_bfloat162 p = *reinterpret_cast<__nv_bfloat162*>(&u);
    return make_float2(__bfloat162float(p.x), __bfloat162float(p.y));
}
__device__ __forceinline__ void mma16(float* d, const uint32_t* a, const uint32_t* b) {
    asm volatile(
        "mma.sync.aligned.m16n8k16.row.col.f32.bf16.bf16.f32 "
        "{%0,%1,%2,%3}, {%4,%5,%6,%7}, {%8,%9}, {%0,%1,%2,%3};"
        : "+f"(d[0]), "+f"(d[1]), "+f"(d[2]), "+f"(d[3])
        : "r"(a[0]), "r"(a[1]), "r"(a[2]), "r"(a[3]), "r"(b[0]), "r"(b[1]));
}
__device__ __forceinline__ void ldsm4(uint32_t* r, uint32_t addr) {
    asm volatile("ldmatrix.sync.aligned.m8n8.x4.shared.b16 {%0,%1,%2,%3}, [%4];"
                 : "=r"(r[0]), "=r"(r[1]), "=r"(r[2]), "=r"(r[3]) : "r"(addr));
}

// BARX (id1): utility arrives (XBF/VB ready), mma syncs. BARS (id3): mma arrives
// (scores ready), utility syncs. PBAR (id2): utility-internal (128 threads).
#define BARX_ARRIVE() asm volatile("bar.arrive 1, 256;" ::: "memory")
#define BARX_SYNC()   asm volatile("bar.sync   1, 256;" ::: "memory")
#define BARS_ARRIVE() asm volatile("bar.arrive 3, 256;" ::: "memory")
#define BARS_SYNC()   asm volatile("bar.sync   3, 256;" ::: "memory")
#define PBAR()        asm volatile("bar.sync   2, 128;" ::: "memory")

// ---------------------------------------------------------------------------
// K1
// ---------------------------------------------------------------------------
__global__ __launch_bounds__(256, 1) void din_attn_kernel(
    const float* __restrict__ beh, const float* __restrict__ cand,
    const float* __restrict__ fc1w, const float* __restrict__ fc1b,
    const float* __restrict__ fc2w, int nb)
{
    extern __shared__ __align__(16) char Ab[];
    const uint32_t A = smem_u32(Ab);

    float* stgF  = (float*)(Ab + STG_OFF);
    float* stgv  = (float*)(Ab + STGV_OFF);
    float* VB    = (float*)(Ab + VB_OFF);
    float* part  = (float*)(Ab + PART_OFF);
    float* attn  = (float*)(Ab + ATTN_OFF);
    float* part2 = (float*)(Ab + PART2_OFF);
    float* red   = (float*)(Ab + RED_OFF);

    const int tid = threadIdx.x, wid = tid >> 5, lane = tid & 31;
    const int g = lane >> 2, t4 = lane & 3;
    const int stride = gridDim.x;
    const int b0 = blockIdx.x;
    if (b0 >= nb) return;

    const bool is_mma = (wid < 4);

    // ================= one-time init (all 256 threads) =================
    {   // stage W_b fp32 (64KB) into staging region
        const float4* w4 = (const float4*)fc1w;
        float4* s4 = (float4*)stgF;
#pragma unroll
        for (int i = 0; i < 16; i++) s4[tid + i * 256] = w4[tid + i * 256];
    }
    __syncthreads();

    // mma warps: warp w owns cols [32w, 32w+32): Bf[8][4][2] = 64 regs + w2 regs
    uint32_t Bf[8][4][2];
    float w2v[4][2];
    if (is_mma) {
        const int n0 = wid * 32;
#pragma unroll
        for (int kt = 0; kt < 8; kt++)
#pragma unroll
            for (int nt = 0; nt < 4; nt++) {
                int n = n0 + nt * 8 + g;
                int r = kt * 16 + 2 * t4;
                Bf[kt][nt][0] = packbf(stgF[r * 128 + n],       stgF[(r + 1) * 128 + n]);
                Bf[kt][nt][1] = packbf(stgF[(r + 8) * 128 + n], stgF[(r + 9) * 128 + n]);
            }
#pragma unroll
        for (int nt = 0; nt < 4; nt++) {
            int c = n0 + nt * 8 + 2 * t4;
            w2v[nt][0] = fc2w[c];
            w2v[nt][1] = fc2w[c + 1];
        }
    }
    __syncthreads();   // W_b staging consumed

    // stage W_c transposed [n][130] fp32 into staging; zero phantom X rows
    for (int idx = tid; idx < 128 * 128; idx += 256) {
        int e = idx >> 7, n = idx & 127;
        stgF[n * 130 + e] = fc1w[128 * 128 + idx];
    }
    for (int i = tid; i < 1088; i += 256) {
        *(uint16_t*)(Ab + XBF0_OFF + 200 * XSTRB + i * 2) = 0;
        *(uint16_t*)(Ab + XBF1_OFF + 200 * XSTRB + i * 2) = 0;
    }
    __syncthreads();

    // ---- precompute v for this CTA's batches -> g_v ----
    {
        float* candsc = part;   // [2][128] scratch
        if (tid < 32)
            asm volatile("cp.async.cg.shared.global [%0], [%1], 16;"
                         :: "r"(A + PART_OFF + (uint32_t)tid * 16u),
                            "l"((const float4*)(cand + (size_t)b0 * 128) + tid)
                         : "memory");
        asm volatile("cp.async.commit_group;" ::: "memory");
        int i = 0;
        for (int b = b0; b < nb; b += stride, i++) {
            asm volatile("cp.async.wait_group 0;" ::: "memory");
            __syncthreads();
            int pr = i & 1;
            if (b + stride < nb && tid < 32)
                asm volatile("cp.async.cg.shared.global [%0], [%1], 16;"
                             :: "r"(A + PART_OFF + (uint32_t)((pr ^ 1) * 512 + tid * 16)),
                                "l"((const float4*)(cand + (size_t)(b + stride) * 128) + tid)
                             : "memory");
            asm volatile("cp.async.commit_group;" ::: "memory");
            int n = tid >> 1, h2 = tid & 1;
            const float* wr = stgF + n * 130 + h2 * 64;
            const float* cd = candsc + pr * 128 + h2 * 64;
            float a = 0.f;
#pragma unroll 8
            for (int k = 0; k < 64; k++) a += cd[k] * wr[k];
            a += __shfl_xor_sync(0xffffffffu, a, 1);
            if (h2 == 0) g_v[(size_t)b * 128 + n] = a + fc1b[n];
        }
        __syncthreads();
    }

    // ================= role split =================
    if (is_mma) {
        // ------------- 4 MMA warps, one per SMSP, 32 cols x all rows -------------
        const int n0 = wid * 32;
        const uint32_t lm_lane = (uint32_t)(lane & 15) * XSTRB
                               + ((lane & 16) ? 16u : 0u);
        int i = 0;
        for (int b = b0; b < nb; b += stride, i++) {
            const int par = i & 1;
            BARX_SYNC();   // XBF[par] + VB[par] ready
            const float* vb = VB + par * 128;
            float2 vv[4];
#pragma unroll
            for (int nt = 0; nt < 4; nt++)
                vv[nt] = *(const float2*)(vb + n0 + nt * 8 + 2 * t4);
            float* pt = part + par * 832 + wid * 208;
            const uint32_t lm_base = A + (par ? XBF1_OFF : XBF0_OFF) + lm_lane;

#pragma unroll
            for (int mt = 0; mt < 13; mt++) {
                uint32_t abase = lm_base + (uint32_t)(mt * 16) * XSTRB;
                float acc[4][4];
#pragma unroll
                for (int nt = 0; nt < 4; nt++)
#pragma unroll
                    for (int j = 0; j < 4; j++) acc[nt][j] = 0.f;
#pragma unroll
                for (int kt = 0; kt < 8; kt++) {
                    uint32_t a[4];
                    ldsm4(a, abase + (uint32_t)(kt * 32));
                    mma16(acc[0], a, Bf[kt][0]);
                    mma16(acc[1], a, Bf[kt][1]);
                    mma16(acc[2], a, Bf[kt][2]);
                    mma16(acc[3], a, Bf[kt][3]);
                }
                float p0 = 0.f, p1 = 0.f;
#pragma unroll
                for (int nt = 0; nt < 4; nt++) {
                    p0 += fmaxf(acc[nt][0] + vv[nt].x, 0.f) * w2v[nt][0]
                        + fmaxf(acc[nt][1] + vv[nt].y, 0.f) * w2v[nt][1];
                    p1 += fmaxf(acc[nt][2] + vv[nt].x, 0.f) * w2v[nt][0]
                        + fmaxf(acc[nt][3] + vv[nt].y, 0.f) * w2v[nt][1];
                }
                p0 += __shfl_xor_sync(0xffffffffu, p0, 1);
                p0 += __shfl_xor_sync(0xffffffffu, p0, 2);
                p1 += __shfl_xor_sync(0xffffffffu, p1, 1);
                p1 += __shfl_xor_sync(0xffffffffu, p1, 2);
                if (t4 == 0) {
                    pt[mt * 16 + g] = p0;
                    if (mt * 16 + 8 + g < S_LEN) pt[mt * 16 + 8 + g] = p1;
                }
            }
            BARS_ARRIVE();   // scores(b) ready
        }
    } else {
        // ------------- 4 utility warps (tid 128..255) -------------
        const int ptid = tid - 128;          // 0..127
        const int uwarp = wid - 4;           // 0..3

        auto issue_load = [&](int b) {
            const float4* src = (const float4*)(beh + (size_t)b * (S_LEN * E_DIM));
#pragma unroll 5
            for (int k = 0; k < 50; k++) {
                int j = ptid + (k << 7);
                asm volatile("cp.async.cg.shared.global [%0], [%1], 16;"
                             :: "r"(A + STG_OFF + (uint32_t)j * 16u), "l"(src + j)
                             : "memory");
            }
            if (ptid < 32)
                asm volatile("cp.async.cg.shared.global [%0], [%1], 16;"
                             :: "r"(A + STGV_OFF + (uint32_t)ptid * 16u),
                                "l"((const float4*)(g_v + (size_t)b * 128) + ptid)
                             : "memory");
        };
        auto convert_v = [&](int buf) {
            char* xb = Ab + (buf ? XBF1_OFF : XBF0_OFF);
#pragma unroll 5
            for (int k = 0; k < 25; k++) {
                int i = ptid + (k << 7);
                const float4* s4 = (const float4*)stgF + 2 * i;
                float4 v0 = s4[0], v1 = s4[1];
                int s = i >> 4, e0 = (i & 15) * 8;
                *(uint4*)(xb + (uint32_t)s * XSTRB + (uint32_t)e0 * 2) =
                    make_uint4(packbf(v0.x, v0.y), packbf(v0.z, v0.w),
                               packbf(v1.x, v1.y), packbf(v1.z, v1.w));
            }
            VB[buf * 128 + ptid] = stgv[ptid];
        };

        // prologue
        issue_load(b0);
        asm volatile("cp.async.commit_group;" ::: "memory");
        asm volatile("cp.async.wait_group 0;" ::: "memory");
        PBAR();
        convert_v(0);
        PBAR();            // convert done before staging reuse
        BARX_ARRIVE();
        if (b0 + stride < nb) {
            issue_load(b0 + stride);
            asm volatile("cp.async.commit_group;" ::: "memory");
        }

        int i = 0;
        for (int b = b0; b < nb; b += stride, i++) {
            const int par = i & 1;
            if (b + stride < nb) {
                asm volatile("cp.async.wait_group 0;" ::: "memory");
                PBAR();
                convert_v(par ^ 1);
                PBAR();    // convert reads of STG done before reissue below
                BARX_ARRIVE();
                if (b + 2 * stride < nb) {
                    issue_load(b + 2 * stride);
                    asm volatile("cp.async.commit_group;" ::: "memory");
                }
            }
            // consume scores(b)
            BARS_SYNC();
            const float* pt = part + par * 832;

            // max-free softmax (scores bounded ~|9|)
            float lsum = 0.f;
#pragma unroll
            for (int j = 0; j < 2; j++) {
                int s = ptid + 128 * j;
                if (s < S_LEN) {
                    float e = __expf(pt[s] + pt[208 + s] + pt[416 + s] + pt[624 + s]);
                    attn[s] = e;
                    lsum += e;
                }
            }
#pragma unroll
            for (int o = 16; o; o >>= 1)
                lsum += __shfl_xor_sync(0xffffffffu, lsum, o);
            if (lane == 0) red[uwarp] = lsum;
            PBAR();
            const float inv = 1.f / (red[0] + red[1] + red[2] + red[3]);

            // ui: 8 rowgroups x 25 rows; 8 e-values per thread
            {
                int e8 = (ptid & 15) * 8;
                int h = ptid >> 4;
                const char* xb = Ab + (par ? XBF1_OFF : XBF0_OFF);
                float a0=0.f,a1=0.f,a2=0.f,a3=0.f,a4=0.f,a5=0.f,a6=0.f,a7=0.f;
                int s0 = h * 25;
#pragma unroll 5
                for (int s = s0; s < s0 + 25; s++) {
                    float w = attn[s];
                    uint4 xv = *(const uint4*)(xb + (uint32_t)s * XSTRB + (uint32_t)e8 * 2);
                    float2 q0 = bf2f(xv.x), q1 = bf2f(xv.y);
                    float2 q2 = bf2f(xv.z), q3 = bf2f(xv.w);
                    a0 += w * q0.x; a1 += w * q0.y;
                    a2 += w * q1.x; a3 += w * q1.y;
                    a4 += w * q2.x; a5 += w * q2.y;
                    a6 += w * q3.x; a7 += w * q3.y;
                }
                *(float4*)(part2 + h * 128 + e8)     = make_float4(a0, a1, a2, a3);
                *(float4*)(part2 + h * 128 + e8 + 4) = make_float4(a4, a5, a6, a7);
                PBAR();
                float s = 0.f;
#pragma unroll
                for (int hh = 0; hh < 8; hh++) s += part2[hh * 128 + ptid];
                g_ui[(size_t)b * 128 + ptid] = s * inv;
                PBAR();   // attn/part2 free for next iteration
            }
        }
    }
}

// ---------------------------------------------------------------------------
// K2: logit[r] = relu([ui|cand]@mlp1 + b1) @ mlp2 + b2   (fp32)
// ---------------------------------------------------------------------------
#define K2_SMEM (32 * 256 * 4 + 2 * 16 * 256 * 4)   // 65536

__global__ __launch_bounds__(256, 1) void din_mlp_kernel(
    const float* __restrict__ cand,
    const float* __restrict__ w1, const float* __restrict__ b1,
    const float* __restrict__ w2, const float* __restrict__ b2,
    float* __restrict__ out, int nb)
{
    extern __shared__ __align__(16) float s2[];
    float* xs = s2;              // 32 x 256
    float* ws = s2 + 8192;       // 2 x 16 x 256
    const uint32_t wsA = smem_u32(ws);

    const int tid = threadIdx.x, lane = tid & 31, w = tid >> 5;
    const int rb = blockIdx.x * 32;

#pragma unroll
    for (int i = 0; i < 4; i++) {
        int idx = tid + i * 256;
        int r = idx >> 5, c4 = idx & 31;
        ((float4*)xs)[r * 64 + c4]      = ((const float4*)(g_ui + (size_t)(rb + r) * 128))[c4];
        ((float4*)xs)[r * 64 + 32 + c4] = ((const float4*)(cand + (size_t)(rb + r) * 128))[c4];
    }

    auto issue = [&](int kt, int buf) {
        const float4* src = (const float4*)(w1 + (size_t)kt * 4096);
        uint32_t dst = wsA + (uint32_t)buf * 16384u + (uint32_t)tid * 16u;
#pragma unroll
        for (int i = 0; i < 4; i++)
            asm volatile("cp.async.cg.shared.global [%0], [%1], 16;"
                         :: "r"(dst + i * 4096u), "l"(src + tid + i * 256) : "memory");
    };
    issue(0, 0);
    asm volatile("cp.async.commit_group;" ::: "memory");

    float b1l[8], w2l[8];
#pragma unroll
    for (int j = 0; j < 8; j++) {
        b1l[j] = b1[lane * 8 + j];
        w2l[j] = w2[lane * 8 + j];
    }
    float acc[4][8];
#pragma unroll
    for (int i = 0; i < 4; i++)
#pragma unroll
        for (int j = 0; j < 8; j++) acc[i][j] = 0.f;

    for (int kt = 0; kt < 16; kt++) {
        asm volatile("cp.async.wait_group 0;" ::: "memory");
        __syncthreads();
        if (kt < 15) {
            issue(kt + 1, (kt + 1) & 1);
            asm volatile("cp.async.commit_group;" ::: "memory");
        }
        const float* wt = ws + (kt & 1) * 4096;
#pragma unroll
        for (int kk = 0; kk < 16; kk++) {
            int k = kt * 16 + kk;
            float x0 = xs[(4 * w + 0) * 256 + k];
            float x1 = xs[(4 * w + 1) * 256 + k];
            float x2 = xs[(4 * w + 2) * 256 + k];
            float x3 = xs[(4 * w + 3) * 256 + k];
            float4 a4 = *(const float4*)(wt + kk * 256 + lane * 8);
            float4 c4 = *(const float4*)(wt + kk * 256 + lane * 8 + 4);
            float wb[8] = {a4.x, a4.y, a4.z, a4.w, c4.x, c4.y, c4.z, c4.w};
#pragma unroll
            for (int j = 0; j < 8; j++) {
                acc[0][j] += x0 * wb[j];
                acc[1][j] += x1 * wb[j];
                acc[2][j] += x2 * wb[j];
                acc[3][j] += x3 * wb[j];
            }
        }
    }

    float p[4];
#pragma unroll
    for (int i = 0; i < 4; i++) {
        float s = 0.f;
#pragma unroll
        for (int j = 0; j < 8; j++)
            s += fmaxf(acc[i][j] + b1l[j], 0.f) * w2l[j];
        p[i] = s;
    }
#pragma unroll
    for (int o = 16; o; o >>= 1) {
#pragma unroll
        for (int i = 0; i < 4; i++)
            p[i] += __shfl_xor_sync(0xffffffffu, p[i], o);
    }
    if (lane == 0) {
        float bb = b2[0];
#pragma unroll
        for (int i = 0; i < 4; i++)
            out[rb + 4 * w + i] = p[i] + bb;
    }
}

// ---------------------------------------------------------------------------
extern "C" void kernel_launch(void* const* d_in, const int* in_sizes, int n_in,
                              void* d_out, int out_size)
{
    const float* beh  = (const float*)d_in[0];
    const float* cand = (const float*)d_in[1];
    const float* fc1w = (const float*)d_in[2];
    const float* fc1b = (const float*)d_in[3];
    const float* fc2w = (const float*)d_in[4];
    // d_in[5] = fc2_b: softmax shift-invariant, unused.
    const float* m1w  = (const float*)d_in[6];
    const float* m1b  = (const float*)d_in[7];
    const float* m2w  = (const float*)d_in[8];
    const float* m2b  = (const float*)d_in[9];
    float* out = (float*)d_out;

    const int nb = in_sizes[1] / 128;   // 4096

    int sms = 148;
    cudaDeviceGetAttribute(&sms, cudaDevAttrMultiProcessorCount, 0);

    cudaFuncSetAttribute(din_attn_kernel,
                         cudaFuncAttributeMaxDynamicSharedMemorySize, SMEM_REQ);
    cudaFuncSetAttribute(din_mlp_kernel,
                         cudaFuncAttributeMaxDynamicSharedMemorySize, K2_SMEM);

    int grid1 = sms < nb ? sms : nb;
    din_attn_kernel<<<grid1, 256, SMEM_REQ>>>(beh, cand, fc1w, fc1b, fc2w, nb);

    din_mlp_kernel<<<nb / 32, 256, K2_SMEM>>>(cand, m1w, m1b, m2w, m2b, out, nb);
}